// round 8
// baseline (speedup 1.0000x reference)
#include <cuda_runtime.h>
#include <cuda_bf16.h>
#include <math.h>

#define BB   128
#define SS   1024
#define TT   257
#define VV   256
#define EE   128
#define HH   512
#define GG   2048
#define DSTEPS 256
#define NCTA 128
#define NTH  512
#define WPAD 516
#define HB   (HH * BB)

typedef unsigned long long ull;

// ---------------- device globals ----------------
__device__ float g_tabE[VV * GG];
__device__ float g_tabD[VV * GG];
__device__ float g_b1e[GG];
__device__ float g_b1d[GG];
__device__ float g_fcT[HH * VV];                 // [k][v]
__device__ float g_y0T[(size_t)SS * HB];         // encoder L0 outputs, [s][u][b]
__device__ float g_h0TA[HB], g_h0TB[HB];
__device__ float g_h1TA[HB], g_h1TB[HB];
__device__ float g_h1[BB * HH];                  // plain layout for fc
__device__ int   g_tok[BB];
__device__ int   g_arrive;
__device__ int   g_gen;

// ---------------- helpers ----------------
__device__ __forceinline__ ull pk2(float lo, float hi) {
    ull r; asm("mov.b64 %0, {%1, %2};" : "=l"(r) : "f"(lo), "f"(hi)); return r;
}
__device__ __forceinline__ void fma2(ull& d, ull a, ull b) {
    asm("fma.rn.f32x2 %0, %1, %2, %0;" : "+l"(d) : "l"(a), "l"(b));
}
__device__ __forceinline__ void cp16(float* dst_smem, const float* src) {
    unsigned s = (unsigned)__cvta_generic_to_shared(dst_smem);
    asm volatile("cp.async.cg.shared.global [%0], [%1], 16;" :: "r"(s), "l"(src));
}
#define CP_COMMIT() asm volatile("cp.async.commit_group;")
#define CP_WAIT0()  asm volatile("cp.async.wait_group 0;")
#define CP_WAIT1()  asm volatile("cp.async.wait_group 1;")

__device__ __forceinline__ void gbar() {
    __syncthreads();
    if (threadIdx.x == 0) {
        volatile int* vgen = &g_gen;
        int gen = *vgen;
        __threadfence();
        int t = atomicAdd(&g_arrive, 1);
        if (t == NCTA - 1) {
            atomicExch(&g_arrive, 0);
            __threadfence();
            atomicAdd(&g_gen, 1);
        } else {
            while (*vgen == gen) { }
        }
        __threadfence();
    }
    __syncthreads();
}

// ---------------- init kernels ----------------
__global__ void table_kernel(float* __restrict__ tab,
                             const float* __restrict__ emb,
                             const float* __restrict__ w_ih,
                             const float* __restrict__ b_ih,
                             const float* __restrict__ b_hh) {
    const int v = blockIdx.x;
    __shared__ float es[EE];
    if (threadIdx.x < EE) es[threadIdx.x] = emb[v * EE + threadIdx.x];
    __syncthreads();
    for (int j = threadIdx.x; j < GG; j += blockDim.x) {
        float a = b_ih[j] + b_hh[j];
        const float* w = w_ih + (size_t)j * EE;
#pragma unroll 8
        for (int e = 0; e < EE; e++) a += es[e] * w[e];
        tab[(size_t)v * GG + j] = a;
    }
}

__global__ void misc_init_kernel(const int* __restrict__ trg,
                                 const float* __restrict__ be_ih1, const float* __restrict__ be_hh1,
                                 const float* __restrict__ bd_ih1, const float* __restrict__ bd_hh1,
                                 const float* __restrict__ fc_w) {
    const int tid = blockIdx.x * blockDim.x + threadIdx.x;
    const int n = gridDim.x * blockDim.x;
    for (int i = tid; i < HB; i += n) {
        g_h0TA[i] = 0.f; g_h0TB[i] = 0.f;
        g_h1TA[i] = 0.f; g_h1TB[i] = 0.f;
    }
    for (int j = tid; j < GG; j += n) {
        g_b1e[j] = be_ih1[j] + be_hh1[j];
        g_b1d[j] = bd_ih1[j] + bd_hh1[j];
    }
    for (int i = tid; i < HH * VV; i += n) {
        int k = i >> 8, v = i & 255;
        g_fcT[i] = fc_w[v * HH + k];
    }
    for (int b = tid; b < BB; b += n) g_tok[b] = trg[b * TT];
}

// ---------------- persistent kernel pieces ----------------
struct Smem {
    float* As;    // 16 warps x (2 bufs x 16k x 32rows) = 16384 floats
    float* Ws0;   // [16][WPAD]
    float* Wsx;
    float* Wsh;
    float* gbuf;  // [4][16][130]
    float* cs0;   // [4][128]
    float* cs1;
    int*   tks;   // [128]
};

__device__ __forceinline__ void load_wslice(float* dst, const float* __restrict__ W, int u0) {
    for (int idx = threadIdx.x; idx < 16 * HH; idx += NTH) {
        int c = idx >> 9, k = idx & 511;
        int j = (c >> 2) * HH + u0 + (c & 3);
        dst[c * WPAD + k] = W[(size_t)j * HH + k];
    }
}

// stage one 16k x 32row chunk for this warp (2 KB) via cp.async
// dst layout: [k][32 rows]
__device__ __forceinline__ void stage_warp(float* dst, const float* __restrict__ srcT,
                                           int kbase, int lane, int wr0) {
#pragma unroll
    for (int i = 0; i < 4; i++) {
        int idx = i * 32 + lane;            // 0..127, 16B each
        int k = idx >> 3, j4 = idx & 7;
        cp16(dst + k * 32 + j4 * 4, srcT + (size_t)(kbase + k) * 128 + wr0 + j4 * 4);
    }
}

// warp-autonomous partial GEMM over this warp's 128-k quarter.
// warp: 32 rows x 16 cols; thread: 8 rows x 2 cols.
__device__ __forceinline__ void mma128w(const float* __restrict__ srcT,
                                        const float* __restrict__ Wsm,
                                        float* wbuf, ull accA[4], ull accB[4],
                                        int lane, int wr0, int lr0,
                                        int c0, int c1, int koff) {
    const float* wpa = Wsm + c0 * WPAD + koff;
    const float* wpb = Wsm + c1 * WPAD + koff;
    stage_warp(wbuf, srcT, koff, lane, wr0);
    CP_COMMIT();
#pragma unroll 1
    for (int ch = 0; ch < 8; ch++) {
        const float* cur = wbuf + (ch & 1) * 512;
        if (ch < 7) {
            stage_warp(wbuf + ((ch + 1) & 1) * 512, srcT, koff + (ch + 1) * 16, lane, wr0);
            CP_COMMIT();
            CP_WAIT1();
        } else {
            CP_WAIT0();
        }
        __syncwarp();
#pragma unroll
        for (int k4 = 0; k4 < 4; k4++) {
            float4 wa = *(const float4*)&wpa[ch * 16 + k4 * 4];
            float4 wb = *(const float4*)&wpb[ch * 16 + k4 * 4];
#pragma unroll
            for (int kk = 0; kk < 4; kk++) {
                int ko = k4 * 4 + kk;
                ulonglong2 qa = *(const ulonglong2*)&cur[ko * 32 + lr0];
                ulonglong2 qb = *(const ulonglong2*)&cur[ko * 32 + lr0 + 4];
                float wva = (kk == 0) ? wa.x : (kk == 1) ? wa.y : (kk == 2) ? wa.z : wa.w;
                float wvb = (kk == 0) ? wb.x : (kk == 1) ? wb.y : (kk == 2) ? wb.z : wb.w;
                ull wa2 = pk2(wva, wva);
                ull wb2 = pk2(wvb, wvb);
                fma2(accA[0], qa.x, wa2);
                fma2(accA[1], qa.y, wa2);
                fma2(accA[2], qb.x, wa2);
                fma2(accA[3], qb.y, wa2);
                fma2(accB[0], qa.x, wb2);
                fma2(accB[1], qa.y, wb2);
                fma2(accB[2], qb.x, wb2);
                fma2(accB[3], qb.y, wb2);
            }
        }
        __syncwarp();
    }
}

template<bool HAS_TOK, bool HAS_X, bool WRITE_PLAIN>
__device__ __forceinline__ void lstm_step_dev(const Smem& sm,
                                              const float* __restrict__ tab,
                                              const float* __restrict__ bias,
                                              const float* __restrict__ xT,
                                              const float* __restrict__ Wx,
                                              const float* __restrict__ hT,
                                              const float* __restrict__ Wh,
                                              float* __restrict__ cs,
                                              float* __restrict__ hT_out,
                                              float* __restrict__ h_plain,
                                              int u0) {
    const int tid  = threadIdx.x;
    const int lane = tid & 31;
    const int w    = tid >> 5;
    const int kq   = w >> 2;              // K-quarter 0..3
    const int wr0  = (w & 3) * 32;        // warp's first batch row
    const int lr0  = (lane >> 3) * 8;     // local row base within warp's 32
    const int r0   = wr0 + lr0;           // global batch row base
    const int cp   = lane & 7;            // colpair
    const int c0   = 2 * cp, c1 = 2 * cp + 1;
    const int koff = kq * 128;
    const int jc0  = (c0 >> 2) * HH + u0 + (c0 & 3);
    const int jc1  = (c1 >> 2) * HH + u0 + (c1 & 3);
    float* wbuf = sm.As + w * 1024;

    ull accA[4], accB[4];
    if (kq == 0) {
        if (HAS_TOK) {
#pragma unroll
            for (int rp = 0; rp < 4; rp++) {
                int ta = sm.tks[r0 + 2 * rp];
                int tb = sm.tks[r0 + 2 * rp + 1];
                accA[rp] = pk2(tab[(size_t)ta * GG + jc0], tab[(size_t)tb * GG + jc0]);
                accB[rp] = pk2(tab[(size_t)ta * GG + jc1], tab[(size_t)tb * GG + jc1]);
            }
        } else {
            float b0 = bias[jc0], b1 = bias[jc1];
            ull b02 = pk2(b0, b0), b12 = pk2(b1, b1);
#pragma unroll
            for (int rp = 0; rp < 4; rp++) { accA[rp] = b02; accB[rp] = b12; }
        }
    } else {
#pragma unroll
        for (int rp = 0; rp < 4; rp++) { accA[rp] = 0ULL; accB[rp] = 0ULL; }
    }

    if (HAS_X) mma128w(xT, Wx, wbuf, accA, accB, lane, wr0, lr0, c0, c1, koff);
    mma128w(hT, Wh, wbuf, accA, accB, lane, wr0, lr0, c0, c1, koff);

#pragma unroll
    for (int rp = 0; rp < 4; rp++) {
        *(ull*)&sm.gbuf[kq * 2080 + c0 * 130 + r0 + 2 * rp] = accA[rp];
        *(ull*)&sm.gbuf[kq * 2080 + c1 * 130 + r0 + 2 * rp] = accB[rp];
    }
    __syncthreads();

    // 512 (b, uu) pairs, one per thread; sum the 4 K-quarter partials
    const int b = tid & 127;
    const int uu = tid >> 7;
    {
        float gi = (sm.gbuf[(0 * 4 + uu) * 130 + b] + sm.gbuf[2080 + (0 * 4 + uu) * 130 + b])
                 + (sm.gbuf[4160 + (0 * 4 + uu) * 130 + b] + sm.gbuf[6240 + (0 * 4 + uu) * 130 + b]);
        float gf = (sm.gbuf[(1 * 4 + uu) * 130 + b] + sm.gbuf[2080 + (1 * 4 + uu) * 130 + b])
                 + (sm.gbuf[4160 + (1 * 4 + uu) * 130 + b] + sm.gbuf[6240 + (1 * 4 + uu) * 130 + b]);
        float gg = (sm.gbuf[(2 * 4 + uu) * 130 + b] + sm.gbuf[2080 + (2 * 4 + uu) * 130 + b])
                 + (sm.gbuf[4160 + (2 * 4 + uu) * 130 + b] + sm.gbuf[6240 + (2 * 4 + uu) * 130 + b]);
        float go = (sm.gbuf[(3 * 4 + uu) * 130 + b] + sm.gbuf[2080 + (3 * 4 + uu) * 130 + b])
                 + (sm.gbuf[4160 + (3 * 4 + uu) * 130 + b] + sm.gbuf[6240 + (3 * 4 + uu) * 130 + b]);
        float cold = cs[uu * 128 + b];
        float ig = 1.f / (1.f + expf(-gi));
        float fg = 1.f / (1.f + expf(-gf));
        float og = 1.f / (1.f + expf(-go));
        float cn = fg * cold + ig * tanhf(gg);
        float hn = og * tanhf(cn);
        cs[uu * 128 + b] = cn;
        hT_out[(u0 + uu) * 128 + b] = hn;
        if (WRITE_PLAIN) h_plain[b * HH + u0 + uu] = hn;
    }
    __syncthreads();
}

__device__ __forceinline__ void fc_step(const Smem& sm, int t,
                                        const float* __restrict__ fc_b,
                                        float* __restrict__ out) {
    const int b = blockIdx.x;
    const int tid = threadIdx.x;
    float* h1s  = sm.gbuf;              // 512
    float* part = sm.gbuf + 512;        // 512
    float* rv   = sm.gbuf + 1024;       // 256
    int*   ri   = (int*)(sm.gbuf + 1024 + 256);

    h1s[tid] = g_h1[b * HH + tid];
    __syncthreads();

    const int v = tid & 255;
    const int half = tid >> 8;
    float acc = half ? 0.f : fc_b[v];
    const int k0 = half * 256;
#pragma unroll 8
    for (int k = k0; k < k0 + 256; k++) acc += h1s[k] * g_fcT[k * VV + v];
    part[half * 256 + v] = acc;
    __syncthreads();

    if (tid < 256) {
        float tot = part[tid] + part[256 + tid];
        out[((size_t)b * DSTEPS + t) * VV + tid] = tot;
        rv[tid] = tot; ri[tid] = tid;
    }
    __syncthreads();
    for (int offs = 128; offs > 0; offs >>= 1) {
        if (tid < offs) {
            float o = rv[tid + offs]; int oi = ri[tid + offs];
            if (o > rv[tid] || (o == rv[tid] && oi < ri[tid])) { rv[tid] = o; ri[tid] = oi; }
        }
        __syncthreads();
    }
    if (tid == 0) g_tok[b] = ri[0];
    __syncthreads();
}

// ---------------- the persistent kernel ----------------
__global__ void __launch_bounds__(NTH, 1)
seq2seq_persistent(const int* __restrict__ src,
                   const float* __restrict__ eWhh0,
                   const float* __restrict__ eWih1, const float* __restrict__ eWhh1,
                   const float* __restrict__ dWhh0,
                   const float* __restrict__ dWih1, const float* __restrict__ dWhh1,
                   const float* __restrict__ fc_b,
                   float* __restrict__ out) {
    extern __shared__ float smraw[];
    Smem sm;
    sm.As  = smraw;                    // 16384
    sm.Ws0 = smraw + 16384;
    sm.Wsx = sm.Ws0 + 16 * WPAD;
    sm.Wsh = sm.Wsx + 16 * WPAD;
    sm.gbuf = sm.Wsh + 16 * WPAD;      // 4 x 16 x 130 = 8320
    sm.cs0 = sm.gbuf + 8320;
    sm.cs1 = sm.cs0 + 512;
    sm.tks = (int*)(sm.cs1 + 512);

    const int tid = threadIdx.x;
    const int u0 = blockIdx.x * 4;

    load_wslice(sm.Ws0, eWhh0, u0);
    load_wslice(sm.Wsx, eWih1, u0);
    load_wslice(sm.Wsh, eWhh1, u0);
    for (int i = tid; i < 512; i += NTH) { sm.cs0[i] = 0.f; sm.cs1[i] = 0.f; }
    __syncthreads();

    // ===== fused encoder: L0 step tau + L1 step tau-1 per gbar interval =====
    const float* h0cur = g_h0TA;
    float* h1cur = g_h1TA;
    float* h1nxt = g_h1TB;
    for (int tau = 0; tau <= SS; tau++) {
        if (tau < SS) {
            if (tid < BB) sm.tks[tid] = src[tid * SS + tau];
            __syncthreads();
            float* yT = g_y0T + (size_t)tau * HB;
            lstm_step_dev<true, false, false>(sm, g_tabE, nullptr, nullptr, nullptr,
                                              h0cur, sm.Ws0, sm.cs0, yT, nullptr, u0);
            h0cur = yT;
        }
        if (tau >= 1) {
            const float* xT = g_y0T + (size_t)(tau - 1) * HB;
            lstm_step_dev<false, true, false>(sm, nullptr, g_b1e, xT, sm.Wsx,
                                              h1cur, sm.Wsh, sm.cs1, h1nxt, nullptr, u0);
            float* tt = h1cur; h1cur = h1nxt; h1nxt = tt;
        }
        gbar();
    }

    // ===== decoder =====
    load_wslice(sm.Ws0, dWhh0, u0);
    load_wslice(sm.Wsx, dWih1, u0);
    load_wslice(sm.Wsh, dWhh1, u0);
    __syncthreads();
    const float* h0cur2 = g_y0T + (size_t)(SS - 1) * HB;
    float* h0bufs[2] = { g_h0TA, g_h0TB };
    for (int t = 0; t < DSTEPS; t++) {
        if (tid < BB) sm.tks[tid] = g_tok[tid];
        __syncthreads();
        float* h0nxt = h0bufs[t & 1];
        lstm_step_dev<true, false, false>(sm, g_tabD, nullptr, nullptr, nullptr,
                                          h0cur2, sm.Ws0, sm.cs0, h0nxt, nullptr, u0);
        gbar();
        lstm_step_dev<false, true, true>(sm, nullptr, g_b1d, h0nxt, sm.Wsx,
                                         h1cur, sm.Wsh, sm.cs1, h1nxt, g_h1, u0);
        gbar();
        fc_step(sm, t, fc_b, out);
        gbar();
        h0cur2 = h0nxt;
        float* tt = h1cur; h1cur = h1nxt; h1nxt = tt;
    }
}

// ---------------- host launch ----------------
extern "C" void kernel_launch(void* const* d_in, const int* in_sizes, int n_in,
                              void* d_out, int out_size) {
    const int*   src       = (const int*)d_in[0];
    const int*   trg       = (const int*)d_in[1];
    const float* enc_emb   = (const float*)d_in[2];
    const float* enc_w_ih0 = (const float*)d_in[3];
    const float* enc_w_hh0 = (const float*)d_in[4];
    const float* enc_b_ih0 = (const float*)d_in[5];
    const float* enc_b_hh0 = (const float*)d_in[6];
    const float* enc_w_ih1 = (const float*)d_in[7];
    const float* enc_w_hh1 = (const float*)d_in[8];
    const float* enc_b_ih1 = (const float*)d_in[9];
    const float* enc_b_hh1 = (const float*)d_in[10];
    const float* dec_emb   = (const float*)d_in[11];
    const float* dec_w_ih0 = (const float*)d_in[12];
    const float* dec_w_hh0 = (const float*)d_in[13];
    const float* dec_b_ih0 = (const float*)d_in[14];
    const float* dec_b_hh0 = (const float*)d_in[15];
    const float* dec_w_ih1 = (const float*)d_in[16];
    const float* dec_w_hh1 = (const float*)d_in[17];
    const float* dec_b_ih1 = (const float*)d_in[18];
    const float* dec_b_hh1 = (const float*)d_in[19];
    const float* fc_w      = (const float*)d_in[20];
    const float* fc_b      = (const float*)d_in[21];
    float* out = (float*)d_out;

    float* tabE; cudaGetSymbolAddress((void**)&tabE, g_tabE);
    float* tabD; cudaGetSymbolAddress((void**)&tabD, g_tabD);

    static int smem_set = 0;
    const int SMEM_BYTES = (16384 + 3 * 16 * WPAD + 8320 + 512 + 512 + 128) * 4;
    if (!smem_set) {
        cudaFuncSetAttribute(seq2seq_persistent,
                             cudaFuncAttributeMaxDynamicSharedMemorySize, SMEM_BYTES);
        smem_set = 1;
    }

    table_kernel<<<VV, 256>>>(tabE, enc_emb, enc_w_ih0, enc_b_ih0, enc_b_hh0);
    table_kernel<<<VV, 256>>>(tabD, dec_emb, dec_w_ih0, dec_b_ih0, dec_b_hh0);
    misc_init_kernel<<<256, 256>>>(trg, enc_b_ih1, enc_b_hh1, dec_b_ih1, dec_b_hh1, fc_w);

    seq2seq_persistent<<<NCTA, NTH, SMEM_BYTES>>>(
        src, enc_w_hh0, enc_w_ih1, enc_w_hh1,
        dec_w_hh0, dec_w_ih1, dec_w_hh1, fc_b, out);

    (void)in_sizes; (void)n_in; (void)out_size;
}

// round 10
// speedup vs baseline: 1.2551x; 1.2551x over previous
#include <cuda_runtime.h>
#include <cuda_bf16.h>
#include <math.h>

#define BB   128
#define SS   1024
#define TT   257
#define VV   256
#define EE   128
#define HH   512
#define GG   2048
#define DSTEPS 256
#define NCTA 128
#define NTH  512
#define WPAD 516          // decoder weight row stride (16B aligned)
#define UPAD 516          // encoder weight row stride (16B aligned; was 513 -> misaligned LDS.128)
#define HB   (HH * BB)

typedef unsigned long long ull;

// ---------------- device globals ----------------
__device__ float g_tabE[VV * GG];
__device__ float g_tabD[VV * GG];
__device__ float g_b1e[GG];
__device__ float g_b1d[GG];
__device__ float g_fcT[HH * VV];                 // [k][v]
__device__ float g_y0T[(size_t)SS * HB];         // encoder L0 outputs, [s][u][b]
__device__ float g_h0TA[HB], g_h0TB[HB];
__device__ float g_h1TA[HB], g_h1TB[HB];
__device__ float g_c0T[HB], g_c1T[HB];           // cell states across phase change
__device__ float g_h1[BB * HH];                  // plain layout for fc
__device__ int   g_tok[BB];
__device__ int   g_cnt[8];
__device__ int   g_gcnt;
__device__ int   g_gen;

// ---------------- helpers ----------------
__device__ __forceinline__ ull pk2(float lo, float hi) {
    ull r; asm("mov.b64 %0, {%1, %2};" : "=l"(r) : "f"(lo), "f"(hi)); return r;
}
__device__ __forceinline__ void fma2(ull& d, ull a, ull b) {
    asm("fma.rn.f32x2 %0, %1, %2, %0;" : "+l"(d) : "l"(a), "l"(b));
}
__device__ __forceinline__ void cp16(float* dst_smem, const float* src) {
    unsigned s = (unsigned)__cvta_generic_to_shared(dst_smem);
    asm volatile("cp.async.cg.shared.global [%0], [%1], 16;" :: "r"(s), "l"(src));
}
#define CP_COMMIT() asm volatile("cp.async.commit_group;")
#define CP_WAIT0()  asm volatile("cp.async.wait_group 0;")
#define CP_WAIT1()  asm volatile("cp.async.wait_group 1;")

// two-level grid barrier: 8 groups x 16 CTAs
__device__ __forceinline__ void gbar() {
    __syncthreads();
    if (threadIdx.x == 0) {
        const int grp = blockIdx.x >> 4;
        volatile int* vgen = &g_gen;
        int gen = *vgen;
        __threadfence();
        if (atomicAdd(&g_cnt[grp], 1) == 15) {
            atomicExch(&g_cnt[grp], 0);
            if (atomicAdd(&g_gcnt, 1) == 7) {
                atomicExch(&g_gcnt, 0);
                __threadfence();
                atomicAdd(&g_gen, 1);
            } else {
                while (*vgen == gen) { }
            }
        } else {
            while (*vgen == gen) { }
        }
        __threadfence();
    }
    __syncthreads();
}

// ---------------- init kernels ----------------
__global__ void table_kernel(float* __restrict__ tab,
                             const float* __restrict__ emb,
                             const float* __restrict__ w_ih,
                             const float* __restrict__ b_ih,
                             const float* __restrict__ b_hh) {
    const int v = blockIdx.x;
    __shared__ float es[EE];
    if (threadIdx.x < EE) es[threadIdx.x] = emb[v * EE + threadIdx.x];
    __syncthreads();
    for (int j = threadIdx.x; j < GG; j += blockDim.x) {
        float a = b_ih[j] + b_hh[j];
        const float* w = w_ih + (size_t)j * EE;
#pragma unroll 8
        for (int e = 0; e < EE; e++) a += es[e] * w[e];
        tab[(size_t)v * GG + j] = a;
    }
}

__global__ void misc_init_kernel(const int* __restrict__ trg,
                                 const float* __restrict__ be_ih1, const float* __restrict__ be_hh1,
                                 const float* __restrict__ bd_ih1, const float* __restrict__ bd_hh1,
                                 const float* __restrict__ fc_w) {
    const int tid = blockIdx.x * blockDim.x + threadIdx.x;
    const int n = gridDim.x * blockDim.x;
    for (int i = tid; i < HB; i += n) {
        g_h0TA[i] = 0.f; g_h0TB[i] = 0.f;
        g_h1TA[i] = 0.f; g_h1TB[i] = 0.f;
    }
    for (int j = tid; j < GG; j += n) {
        g_b1e[j] = be_ih1[j] + be_hh1[j];
        g_b1d[j] = bd_ih1[j] + bd_hh1[j];
    }
    for (int i = tid; i < HH * VV; i += n) {
        int k = i >> 8, v = i & 255;
        g_fcT[i] = fc_w[v * HH + k];
    }
    for (int b = tid; b < BB; b += n) g_tok[b] = trg[b * TT];
}

// ============================================================
// ENCODER geometry: CTA = 8 units (32 gate-cols) x 64 batch rows
// 16 warps: kq = w>>3 (K halves of 256), warp rows = (w&7)*8..+8
// lane = gate-col (32); thread tile 8 rows x 1 col
// ============================================================

// smem offsets (floats), encoder phases (UPAD=516)
#define E_WA   0
#define E_WB   16512     // 32*516
#define E_AS   33024     // + 32*516
#define E_GB   49408     // + 16*1024 ; 2 x 32 x 66 = 4224
#define E_CS   53632     // 512
#define E_TKS  54144     // 64 ints
#define E_TOTAL 54208

__device__ __forceinline__ void load_wslice_u8(float* dst, const float* __restrict__ W, int u0) {
    for (int idx = threadIdx.x; idx < 32 * HH; idx += NTH) {
        int c = idx >> 9, k = idx & 511;
        int j = (c >> 3) * HH + u0 + (c & 7);
        dst[c * UPAD + k] = W[(size_t)j * HH + k];
    }
}

// stage 64k x 8rows (2KB) for this warp
__device__ __forceinline__ void stage_u8(float* dst, const float* __restrict__ srcT,
                                         int kbase, int lane, int gr0) {
#pragma unroll
    for (int i = 0; i < 4; i++) {
        int idx = i * 32 + lane;         // 0..127 cp16 ops
        int k = idx >> 1, half = idx & 1;
        cp16(dst + k * 8 + half * 4, srcT + (size_t)(kbase + k) * 128 + gr0 + half * 4);
    }
}

// warp-autonomous partial GEMM over a 256-k half; thread 8 rows x 1 col
__device__ __forceinline__ void mma256_u8(const float* __restrict__ srcT,
                                          const float* __restrict__ Wsm,
                                          float* wbuf, ull acc[4],
                                          int lane, int gr0, int koff, int c) {
    const float* wp = Wsm + c * UPAD + koff;
    stage_u8(wbuf, srcT, koff, lane, gr0);
    CP_COMMIT();
#pragma unroll 1
    for (int ch = 0; ch < 4; ch++) {
        const float* cur = wbuf + (ch & 1) * 512;
        if (ch < 3) {
            stage_u8(wbuf + ((ch + 1) & 1) * 512, srcT, koff + (ch + 1) * 64, lane, gr0);
            CP_COMMIT();
            CP_WAIT1();
        } else {
            CP_WAIT0();
        }
        __syncwarp();
#pragma unroll
        for (int k4 = 0; k4 < 16; k4++) {
            float4 wv = *(const float4*)&wp[ch * 64 + k4 * 4];
#pragma unroll
            for (int kk = 0; kk < 4; kk++) {
                int ko = k4 * 4 + kk;
                ulonglong2 qa = *(const ulonglong2*)&cur[ko * 8];
                ulonglong2 qb = *(const ulonglong2*)&cur[ko * 8 + 4];
                float w = (kk == 0) ? wv.x : (kk == 1) ? wv.y : (kk == 2) ? wv.z : wv.w;
                ull w2 = pk2(w, w);
                fma2(acc[0], qa.x, w2);
                fma2(acc[1], qa.y, w2);
                fma2(acc[2], qb.x, w2);
                fma2(acc[3], qb.y, w2);
            }
        }
        __syncwarp();
    }
}

template<bool HAS_TOK, bool HAS_X>
__device__ __forceinline__ void lstm_step_u8(float* smraw,
                                             const float* __restrict__ tab,
                                             const float* __restrict__ bias,
                                             const float* __restrict__ xT,
                                             const float* __restrict__ hT,
                                             float* __restrict__ hT_out,
                                             int u0, int b0) {
    float* Wa   = smraw + E_WA;
    float* Wb   = smraw + E_WB;
    float* As   = smraw + E_AS;
    float* gbuf = smraw + E_GB;
    float* cs   = smraw + E_CS;
    int*   tks  = (int*)(smraw + E_TKS);

    const int tid  = threadIdx.x;
    const int lane = tid & 31;
    const int w    = tid >> 5;
    const int kq   = w >> 3;
    const int wr   = (w & 7) * 8;       // local row base
    const int koff = kq * 256;
    const int c    = lane;              // gate-col 0..31
    const int jc   = (c >> 3) * HH + u0 + (c & 7);
    const int gr0  = b0 + wr;           // global row base
    float* wbuf = As + w * 1024;

    ull acc[4];
    if (kq == 0) {
        if (HAS_TOK) {
#pragma unroll
            for (int rp = 0; rp < 4; rp++) {
                int ta = tks[wr + 2 * rp];
                int tb = tks[wr + 2 * rp + 1];
                acc[rp] = pk2(tab[(size_t)ta * GG + jc], tab[(size_t)tb * GG + jc]);
            }
        } else {
            float bv = bias[jc];
            ull b2 = pk2(bv, bv);
#pragma unroll
            for (int rp = 0; rp < 4; rp++) acc[rp] = b2;
        }
    } else {
#pragma unroll
        for (int rp = 0; rp < 4; rp++) acc[rp] = 0ULL;
    }

    if (HAS_X) mma256_u8(xT, Wa, wbuf, acc, lane, gr0, koff, c);
    mma256_u8(hT, HAS_X ? Wb : Wa, wbuf, acc, lane, gr0, koff, c);

#pragma unroll
    for (int rp = 0; rp < 4; rp++)
        *(ull*)&gbuf[kq * 2112 + c * 66 + wr + 2 * rp] = acc[rp];
    __syncthreads();

    // state update: thread -> (uu = tid>>6, b = tid&63)
    const int b  = tid & 63;
    const int uu = tid >> 6;
    {
        float gi = gbuf[(0 * 8 + uu) * 66 + b] + gbuf[2112 + (0 * 8 + uu) * 66 + b];
        float gf = gbuf[(1 * 8 + uu) * 66 + b] + gbuf[2112 + (1 * 8 + uu) * 66 + b];
        float gg = gbuf[(2 * 8 + uu) * 66 + b] + gbuf[2112 + (2 * 8 + uu) * 66 + b];
        float go = gbuf[(3 * 8 + uu) * 66 + b] + gbuf[2112 + (3 * 8 + uu) * 66 + b];
        float cold = cs[uu * 64 + b];
        float ig = 1.f / (1.f + expf(-gi));
        float fg = 1.f / (1.f + expf(-gf));
        float og = 1.f / (1.f + expf(-go));
        float cn = fg * cold + ig * tanhf(gg);
        float hn = og * tanhf(cn);
        cs[uu * 64 + b] = cn;
        hT_out[(u0 + uu) * 128 + b0 + b] = hn;
    }
    __syncthreads();
}

// ============================================================
// DECODER geometry: R7-proven. CTA = 4 units (16 cols) x 128 rows,
// 16 warps, ksplit2, warp = 16 rows x 16 cols, thread 8 rows x 1 col
// ============================================================

// smem offsets (floats), decoder
#define D_W0   0
#define D_WX   8256
#define D_WH   16512
#define D_AS   24768
#define D_GB   41152     // 2 x 16 x 130 = 4160
#define D_CS0  45312
#define D_CS1  45824
#define D_TKS  46336

__device__ __forceinline__ void load_wslice_u4(float* dst, const float* __restrict__ W, int u0) {
    for (int idx = threadIdx.x; idx < 16 * HH; idx += NTH) {
        int c = idx >> 9, k = idx & 511;
        int j = (c >> 2) * HH + u0 + (c & 3);
        dst[c * WPAD + k] = W[(size_t)j * HH + k];
    }
}

__device__ __forceinline__ void stage_u4(float* dst, const float* __restrict__ srcT,
                                         int kbase, int lane, int w16) {
#pragma unroll
    for (int i = 0; i < 4; i++) {
        int idx = i * 32 + lane;
        int k = idx >> 2, jq = idx & 3;
        cp16(dst + k * 16 + jq * 4, srcT + (size_t)(kbase + k) * 128 + w16 + jq * 4);
    }
}

__device__ __forceinline__ void mma256_u4(const float* __restrict__ srcT,
                                          const float* __restrict__ Wsm,
                                          float* wbuf, ull acc[4],
                                          int lane, int w16, int lrb8, int cg, int koff) {
    const float* wp = Wsm + cg * WPAD + koff;
    stage_u4(wbuf, srcT, koff, lane, w16);
    CP_COMMIT();
#pragma unroll 1
    for (int ch = 0; ch < 8; ch++) {
        const float* cur = wbuf + (ch & 1) * 512;
        if (ch < 7) {
            stage_u4(wbuf + ((ch + 1) & 1) * 512, srcT, koff + (ch + 1) * 32, lane, w16);
            CP_COMMIT();
            CP_WAIT1();
        } else {
            CP_WAIT0();
        }
        __syncwarp();
#pragma unroll
        for (int k4 = 0; k4 < 8; k4++) {
            float4 wv = *(const float4*)&wp[ch * 32 + k4 * 4];
#pragma unroll
            for (int kk = 0; kk < 4; kk++) {
                int ko = k4 * 4 + kk;
                ulonglong2 qa = *(const ulonglong2*)&cur[ko * 16 + lrb8];
                ulonglong2 qb = *(const ulonglong2*)&cur[ko * 16 + lrb8 + 4];
                float w = (kk == 0) ? wv.x : (kk == 1) ? wv.y : (kk == 2) ? wv.z : wv.w;
                ull w2 = pk2(w, w);
                fma2(acc[0], qa.x, w2);
                fma2(acc[1], qa.y, w2);
                fma2(acc[2], qb.x, w2);
                fma2(acc[3], qb.y, w2);
            }
        }
        __syncwarp();
    }
}

template<bool HAS_TOK, bool HAS_X, bool WRITE_PLAIN>
__device__ __forceinline__ void lstm_step_u4(float* smraw,
                                             const float* __restrict__ tab,
                                             const float* __restrict__ bias,
                                             const float* __restrict__ xT,
                                             const float* __restrict__ Wx,
                                             const float* __restrict__ hT,
                                             const float* __restrict__ Wh,
                                             float* __restrict__ cs,
                                             float* __restrict__ hT_out,
                                             float* __restrict__ h_plain,
                                             int u0) {
    float* As   = smraw + D_AS;
    float* gbuf = smraw + D_GB;
    int*   tks  = (int*)(smraw + D_TKS);

    const int tid  = threadIdx.x;
    const int lane = tid & 31;
    const int wg   = tid >> 8;
    const int t8   = tid & 255;
    const int rg   = t8 >> 4, cg = t8 & 15;
    const int r0   = rg * 8;
    const int lrb8 = (rg & 1) * 8;
    const int w16  = (t8 >> 5) * 16;
    const int koff = wg * 256;
    const int jc   = (cg >> 2) * HH + u0 + (cg & 3);
    float* wbuf = As + (tid >> 5) * 1024;

    ull acc[4];
    if (wg == 0) {
        if (HAS_TOK) {
#pragma unroll
            for (int rp = 0; rp < 4; rp++) {
                int ta = tks[r0 + 2 * rp];
                int tb = tks[r0 + 2 * rp + 1];
                acc[rp] = pk2(tab[(size_t)ta * GG + jc], tab[(size_t)tb * GG + jc]);
            }
        } else {
            float bv = bias[jc];
            ull b2 = pk2(bv, bv);
#pragma unroll
            for (int rp = 0; rp < 4; rp++) acc[rp] = b2;
        }
    } else {
#pragma unroll
        for (int rp = 0; rp < 4; rp++) acc[rp] = 0ULL;
    }

    if (HAS_X) mma256_u4(xT, Wx, wbuf, acc, lane, w16, lrb8, cg, koff);
    mma256_u4(hT, Wh, wbuf, acc, lane, w16, lrb8, cg, koff);

#pragma unroll
    for (int rp = 0; rp < 4; rp++)
        *(ull*)&gbuf[wg * 2080 + cg * 130 + r0 + 2 * rp] = acc[rp];
    __syncthreads();

    const int b = tid & 127;
    const int uu = tid >> 7;
    {
        float gi = gbuf[(0 * 4 + uu) * 130 + b] + gbuf[2080 + (0 * 4 + uu) * 130 + b];
        float gf = gbuf[(1 * 4 + uu) * 130 + b] + gbuf[2080 + (1 * 4 + uu) * 130 + b];
        float gg = gbuf[(2 * 4 + uu) * 130 + b] + gbuf[2080 + (2 * 4 + uu) * 130 + b];
        float go = gbuf[(3 * 4 + uu) * 130 + b] + gbuf[2080 + (3 * 4 + uu) * 130 + b];
        float cold = cs[uu * 128 + b];
        float ig = 1.f / (1.f + expf(-gi));
        float fg = 1.f / (1.f + expf(-gf));
        float og = 1.f / (1.f + expf(-go));
        float cn = fg * cold + ig * tanhf(gg);
        float hn = og * tanhf(cn);
        cs[uu * 128 + b] = cn;
        hT_out[(u0 + uu) * 128 + b] = hn;
        if (WRITE_PLAIN) h_plain[b * HH + u0 + uu] = hn;
    }
    __syncthreads();
}

__device__ __forceinline__ void fc_step(float* smraw, int t,
                                        const float* __restrict__ fc_b,
                                        float* __restrict__ out) {
    float* gbuf = smraw + D_GB;
    const int b = blockIdx.x;
    const int tid = threadIdx.x;
    float* h1s  = gbuf;
    float* part = gbuf + 512;
    float* rv   = gbuf + 1024;
    int*   ri   = (int*)(gbuf + 1024 + 256);

    h1s[tid] = g_h1[b * HH + tid];
    __syncthreads();

    const int v = tid & 255;
    const int half = tid >> 8;
    float acc = half ? 0.f : fc_b[v];
    const int k0 = half * 256;
#pragma unroll 8
    for (int k = k0; k < k0 + 256; k++) acc += h1s[k] * g_fcT[k * VV + v];
    part[half * 256 + v] = acc;
    __syncthreads();

    if (tid < 256) {
        float tot = part[tid] + part[256 + tid];
        out[((size_t)b * DSTEPS + t) * VV + tid] = tot;
        rv[tid] = tot; ri[tid] = tid;
    }
    __syncthreads();
    for (int offs = 128; offs > 0; offs >>= 1) {
        if (tid < offs) {
            float o = rv[tid + offs]; int oi = ri[tid + offs];
            if (o > rv[tid] || (o == rv[tid] && oi < ri[tid])) { rv[tid] = o; ri[tid] = oi; }
        }
        __syncthreads();
    }
    if (tid == 0) g_tok[b] = ri[0];
    __syncthreads();
}

// ---------------- the persistent kernel ----------------
__global__ void __launch_bounds__(NTH, 1)
seq2seq_persistent(const int* __restrict__ src,
                   const float* __restrict__ eWhh0,
                   const float* __restrict__ eWih1, const float* __restrict__ eWhh1,
                   const float* __restrict__ dWhh0,
                   const float* __restrict__ dWih1, const float* __restrict__ dWhh1,
                   const float* __restrict__ fc_b,
                   float* __restrict__ out) {
    extern __shared__ float smraw[];
    const int tid = threadIdx.x;
    const int cta = blockIdx.x;

    // encoder geometry: 64 unit-blocks x 2 batch-blocks
    const int u0e = (cta >> 1) * 8;
    const int b0e = (cta & 1) * 64;
    // decoder geometry
    const int u0d = cta * 4;

    // ===== encoder L0 (U8 x B64) =====
    load_wslice_u8(smraw + E_WA, eWhh0, u0e);
    for (int i = tid; i < 512; i += NTH) smraw[E_CS + i] = 0.f;
    __syncthreads();
    {
        const float* hcur = g_h0TA;   // zeros
        for (int s = 0; s < SS; s++) {
            if (tid < 64) ((int*)(smraw + E_TKS))[tid] = src[(b0e + tid) * SS + s];
            __syncthreads();
            float* yT = g_y0T + (size_t)s * HB;
            lstm_step_u8<true, false>(smraw, g_tabE, nullptr, nullptr, hcur, yT, u0e, b0e);
            hcur = yT;
            gbar();
        }
        // persist c0 to global (decoder reads different slices)
        {
            const int b = tid & 63, uu = tid >> 6;
            g_c0T[(u0e + uu) * 128 + b0e + b] = smraw[E_CS + uu * 64 + b];
        }
    }

    // ===== encoder L1 (U8 x B64) =====
    load_wslice_u8(smraw + E_WA, eWih1, u0e);
    load_wslice_u8(smraw + E_WB, eWhh1, u0e);
    for (int i = tid; i < 512; i += NTH) smraw[E_CS + i] = 0.f;
    __syncthreads();
    {
        float* h1cur = g_h1TA;        // zeros
        float* h1nxt = g_h1TB;
        for (int s = 0; s < SS; s++) {
            const float* xT = g_y0T + (size_t)s * HB;
            lstm_step_u8<false, true>(smraw, nullptr, g_b1e, xT, h1cur, h1nxt, u0e, b0e);
            float* tt = h1cur; h1cur = h1nxt; h1nxt = tt;
            gbar();
        }
        // persist c1
        {
            const int b = tid & 63, uu = tid >> 6;
            g_c1T[(u0e + uu) * 128 + b0e + b] = smraw[E_CS + uu * 64 + b];
        }
    }
    gbar();   // c0T/c1T visible to all before decoder loads

    // ===== decoder (U4 x B128, R7 geometry) =====
    load_wslice_u4(smraw + D_W0, dWhh0, u0d);
    load_wslice_u4(smraw + D_WX, dWih1, u0d);
    load_wslice_u4(smraw + D_WH, dWhh1, u0d);
    __syncthreads();
    {
        const int b = tid & 127, uu = tid >> 7;
        smraw[D_CS0 + uu * 128 + b] = g_c0T[(u0d + uu) * 128 + b];
        smraw[D_CS1 + uu * 128 + b] = g_c1T[(u0d + uu) * 128 + b];
    }
    __syncthreads();

    const float* h0cur = g_y0T + (size_t)(SS - 1) * HB;   // encoder L0 final h
    float* h1cur = g_h1TA;                                // encoder L1 final h (1024 steps even)
    float* h1nxt = g_h1TB;
    float* h0bufs[2] = { g_h0TA, g_h0TB };
    for (int t = 0; t < DSTEPS; t++) {
        if (tid < BB) ((int*)(smraw + D_TKS))[tid] = g_tok[tid];
        __syncthreads();
        float* h0nxt = h0bufs[t & 1];
        lstm_step_u4<true, false, false>(smraw, g_tabD, nullptr, nullptr, nullptr,
                                         h0cur, smraw + D_W0, smraw + D_CS0, h0nxt, nullptr, u0d);
        gbar();
        lstm_step_u4<false, true, true>(smraw, nullptr, g_b1d, h0nxt, smraw + D_WX,
                                        h1cur, smraw + D_WH, smraw + D_CS1, h1nxt, g_h1, u0d);
        gbar();
        fc_step(smraw, t, fc_b, out);
        gbar();
        h0cur = h0nxt;
        float* tt = h1cur; h1cur = h1nxt; h1nxt = tt;
    }
}

// ---------------- host launch ----------------
extern "C" void kernel_launch(void* const* d_in, const int* in_sizes, int n_in,
                              void* d_out, int out_size) {
    const int*   src       = (const int*)d_in[0];
    const int*   trg       = (const int*)d_in[1];
    const float* enc_emb   = (const float*)d_in[2];
    const float* enc_w_ih0 = (const float*)d_in[3];
    const float* enc_w_hh0 = (const float*)d_in[4];
    const float* enc_b_ih0 = (const float*)d_in[5];
    const float* enc_b_hh0 = (const float*)d_in[6];
    const float* enc_w_ih1 = (const float*)d_in[7];
    const float* enc_w_hh1 = (const float*)d_in[8];
    const float* enc_b_ih1 = (const float*)d_in[9];
    const float* enc_b_hh1 = (const float*)d_in[10];
    const float* dec_emb   = (const float*)d_in[11];
    const float* dec_w_ih0 = (const float*)d_in[12];
    const float* dec_w_hh0 = (const float*)d_in[13];
    const float* dec_b_ih0 = (const float*)d_in[14];
    const float* dec_b_hh0 = (const float*)d_in[15];
    const float* dec_w_ih1 = (const float*)d_in[16];
    const float* dec_w_hh1 = (const float*)d_in[17];
    const float* dec_b_ih1 = (const float*)d_in[18];
    const float* dec_b_hh1 = (const float*)d_in[19];
    const float* fc_w      = (const float*)d_in[20];
    const float* fc_b      = (const float*)d_in[21];
    float* out = (float*)d_out;

    float* tabE; cudaGetSymbolAddress((void**)&tabE, g_tabE);
    float* tabD; cudaGetSymbolAddress((void**)&tabD, g_tabD);

    static int smem_set = 0;
    const int SMEM_BYTES = E_TOTAL * 4;   // 216,832 B (encoder layout is larger)
    if (!smem_set) {
        cudaFuncSetAttribute(seq2seq_persistent,
                             cudaFuncAttributeMaxDynamicSharedMemorySize, SMEM_BYTES);
        smem_set = 1;
    }

    table_kernel<<<VV, 256>>>(tabE, enc_emb, enc_w_ih0, enc_b_ih0, enc_b_hh0);
    table_kernel<<<VV, 256>>>(tabD, dec_emb, dec_w_ih0, dec_b_ih0, dec_b_hh0);
    misc_init_kernel<<<256, 256>>>(trg, enc_b_ih1, enc_b_hh1, dec_b_ih1, dec_b_hh1, fc_w);

    seq2seq_persistent<<<NCTA, NTH, SMEM_BYTES>>>(
        src, enc_w_hh0, enc_w_ih1, enc_w_hh1,
        dec_w_hh0, dec_w_ih1, dec_w_hh1, fc_b, out);

    (void)in_sizes; (void)n_in; (void)out_size;
}